// round 16
// baseline (speedup 1.0000x reference)
#include <cuda_runtime.h>
#include <cuda_bf16.h>
#include <cstdint>
#include <math.h>

#define NB 1024
#define NH 2048
#define NV 8192
#define NL 8

// ---------------- device scratch (no allocs allowed) ----------------
__device__ float g_sf32[2][NB * NH];                    // fp32 state ping-pong
__device__ __nv_bfloat16 g_sbf[2][NB * NH];             // bf16 state ping-pong
__device__ __nv_bfloat16 g_hh_bf[(size_t)NL * NH * NH]; // hh as bf16, [l][k][n]

// ---------------- PTX helpers (base ISA only; compiles at compute_103) ------
__device__ __forceinline__ uint32_t smem_u32(const void* p) {
    uint32_t a;
    asm("{ .reg .u64 t; cvta.to.shared.u64 t, %1; cvt.u32.u64 %0, t; }" : "=r"(a) : "l"(p));
    return a;
}
__device__ __forceinline__ void cp16(uint32_t saddr, const void* gaddr) {
    asm volatile("cp.async.cg.shared.global [%0], [%1], 16;" :: "r"(saddr), "l"(gaddr) : "memory");
}
__device__ __forceinline__ void cp_commit() {
    asm volatile("cp.async.commit_group;" ::: "memory");
}
__device__ __forceinline__ void mbar_init(uint32_t mbar, uint32_t cnt) {
    asm volatile("mbarrier.init.shared.b64 [%0], %1;" :: "r"(mbar), "r"(cnt) : "memory");
}
__device__ __forceinline__ void mbar_arrive(uint32_t mbar) {
    asm volatile("mbarrier.arrive.shared.b64 _, [%0];" :: "r"(mbar) : "memory");
}
__device__ __forceinline__ void mbar_wait(uint32_t mbar, uint32_t parity) {
    uint32_t done;
    asm volatile("{ .reg .pred p; mbarrier.try_wait.parity.shared.b64 p, [%1], %2; selp.b32 %0,1,0,p; }"
                 : "=r"(done) : "r"(mbar), "r"(parity) : "memory");
    while (!done) {
        asm volatile("{ .reg .pred p; mbarrier.try_wait.parity.shared.b64 p, [%1], %2; selp.b32 %0,1,0,p; }"
                     : "=r"(done) : "r"(mbar), "r"(parity) : "memory");
    }
}
__device__ __forceinline__ void ldsm_x4(uint32_t& d0, uint32_t& d1, uint32_t& d2, uint32_t& d3,
                                        uint32_t addr) {
    asm volatile("ldmatrix.sync.aligned.m8n8.x4.shared.b16 {%0,%1,%2,%3}, [%4];"
                 : "=r"(d0), "=r"(d1), "=r"(d2), "=r"(d3) : "r"(addr));
}
__device__ __forceinline__ void ldsm_x4_t(uint32_t& d0, uint32_t& d1, uint32_t& d2, uint32_t& d3,
                                          uint32_t addr) {
    asm volatile("ldmatrix.sync.aligned.m8n8.x4.trans.shared.b16 {%0,%1,%2,%3}, [%4];"
                 : "=r"(d0), "=r"(d1), "=r"(d2), "=r"(d3) : "r"(addr));
}
__device__ __forceinline__ void mma16816(float& c0, float& c1, float& c2, float& c3,
                                         uint32_t a0, uint32_t a1, uint32_t a2, uint32_t a3,
                                         uint32_t b0, uint32_t b1) {
    asm volatile(
        "mma.sync.aligned.m16n8k16.row.col.f32.bf16.bf16.f32 "
        "{%0,%1,%2,%3}, {%4,%5,%6,%7}, {%8,%9}, {%0,%1,%2,%3};"
        : "+f"(c0), "+f"(c1), "+f"(c2), "+f"(c3)
        : "r"(a0), "r"(a1), "r"(a2), "r"(a3), "r"(b0), "r"(b1));
}
// accurate fast tanh: (e^{2x}-1)/(e^{2x}+1); err ~1e-6 over our range
__device__ __forceinline__ float fast_tanh(float x) {
    float xc = fminf(fmaxf(x, -8.0f), 8.0f);
    float e = __expf(2.0f * xc);
    return __fdividef(e - 1.0f, e + 1.0f);
}

// ---------------- tiling ----------------
// Round-7 structure, BK widened to 128 (2-stage ring, half the sync ops).
// CTA tile 128x64. 8 consumer warps (4M x 2N, warp tile 32x32) + 1 producer.
constexpr int BM = 128, BN = 64, BK = 128;
constexpr int NCH = NH / BK;        // 16 K-chunks
constexpr int STAGES = 2;
constexpr int PA_B = 272;           // A smem row pitch (128 bf16 = 256B + 16 pad)
constexpr int PB_B = 144;           // B smem row pitch (64 bf16 + 8 pad)
constexpr int A_BYTES = BM * PA_B;  // 34816
constexpr int B_BYTES = BK * PB_B;  // 18432 (B: 128 k-rows x 64 n-cols)
constexpr int BUF = A_BYTES + B_BYTES;       // 53248
constexpr int MBAR_OFF = STAGES * BUF;       // 106496
constexpr int SMEM_TOTAL = MBAR_OFF + STAGES * 16;  // 106528 (x2 CTA = 213K <= 227K)
constexpr int EPI_PITCH = 68;                // fp32 elems (epi: 128*68*4 = 34816 <= BUF)

__global__ __launch_bounds__(288, 2)
void rnn_layer_tc(const __nv_bfloat16* __restrict__ s_bf,
                  const float* __restrict__ s_f32,
                  const __nv_bfloat16* __restrict__ hh_l,  // [NH(k)][NH(n)] bf16
                  const float* __restrict__ ih_l,          // [NV][NH] fp32
                  const int* __restrict__ token,
                  float* __restrict__ out_f32,
                  __nv_bfloat16* __restrict__ out_bf)
{
    extern __shared__ __align__(128) char smem[];
    const uint32_t smem_base = smem_u32(smem);
    const uint32_t mbar_base = smem_base + MBAR_OFF;
    const int tid  = threadIdx.x;
    const int lane = tid & 31;
    const int wid  = tid >> 5;       // 0..7 consumers, 8 producer

    const int colBase = blockIdx.x * BN;
    const int rowBase = blockIdx.y * BM;

    const __nv_bfloat16* a_base = s_bf + (size_t)rowBase * NH;
    const __nv_bfloat16* b_base = hh_l + colBase;

    if (tid == 0) {
#pragma unroll
        for (int s = 0; s < STAGES; s++) {
            mbar_init(mbar_base + s * 16, 32);      // full[s]: producer threads
            mbar_init(mbar_base + s * 16 + 8, 8);   // empty[s]: consumer warps
        }
    }
    __syncthreads();

    float c[2][4][4];
#pragma unroll
    for (int i = 0; i < 2; i++)
#pragma unroll
        for (int j = 0; j < 4; j++)
#pragma unroll
            for (int k = 0; k < 4; k++) c[i][j][k] = 0.0f;

    if (wid == 8) {
        // ================= producer warp =================
        int phase = 1;   // fresh-barrier wait on parity 1 passes immediately
        for (int ch = 0; ch < NCH; ch++) {
            const int s = ch & (STAGES - 1);
            mbar_wait(mbar_base + s * 16 + 8, phase);   // empty[s]
            const uint32_t sa = smem_base + s * BUF;
            const uint32_t sb = sa + A_BYTES;
            const int kt = ch * BK;
#pragma unroll
            for (int i = 0; i < 64; i++) {   // A: 128 rows x 16 x 16B = 2048 cp16
                int idx = i * 32 + lane;
                int r = idx >> 4, cc = idx & 15;
                cp16(sa + r * PA_B + cc * 16, a_base + (size_t)r * NH + kt + cc * 8);
            }
#pragma unroll
            for (int i = 0; i < 32; i++) {   // B: 128 k-rows x 8 x 16B = 1024 cp16
                int idx = i * 32 + lane;
                int r = idx >> 3, cc = idx & 7;
                cp16(sb + r * PB_B + cc * 16, b_base + (size_t)(kt + r) * NH + cc * 8);
            }
            cp_commit();
            if (ch >= 1) {
                asm volatile("cp.async.wait_group 1;" ::: "memory");
                mbar_arrive(mbar_base + ((ch - 1) & (STAGES - 1)) * 16);  // full
            }
            if (s == STAGES - 1) phase ^= 1;
        }
        asm volatile("cp.async.wait_group 0;" ::: "memory");
        mbar_arrive(mbar_base + ((NCH - 1) & (STAGES - 1)) * 16);
    } else {
        // ================= consumer warps (warp tile 32x32) =================
        const int wm = wid & 3;    // 0..3 (M, 32 rows)
        const int wn = wid >> 2;   // 0..1 (N, 32 cols)
        const int lrow = lane & 15;
        const int lseg = (lane >> 4) * 8;
        int phase = 0;
        for (int ch = 0; ch < NCH; ch++) {
            const int s = ch & (STAGES - 1);
            mbar_wait(mbar_base + s * 16, phase);       // full[s]
            const uint32_t sa = smem_base + s * BUF;
            const uint32_t sb = sa + A_BYTES;
#pragma unroll
            for (int ks = 0; ks < 8; ks++) {   // 8 x k16 per 128-chunk
                uint32_t af[2][4], bfr[4][2];
#pragma unroll
                for (int mt = 0; mt < 2; mt++) {
                    uint32_t addr = sa + (wm * 32 + mt * 16 + lrow) * PA_B
                                       + (ks * 16 + lseg) * 2;
                    ldsm_x4(af[mt][0], af[mt][1], af[mt][2], af[mt][3], addr);
                }
#pragma unroll
                for (int np = 0; np < 2; np++) {
                    uint32_t addr = sb + (ks * 16 + lrow) * PB_B
                                       + (wn * 32 + np * 16 + lseg) * 2;
                    uint32_t r0, r1, r2, r3;
                    ldsm_x4_t(r0, r1, r2, r3, addr);
                    bfr[np * 2 + 0][0] = r0; bfr[np * 2 + 0][1] = r1;
                    bfr[np * 2 + 1][0] = r2; bfr[np * 2 + 1][1] = r3;
                }
#pragma unroll
                for (int mt = 0; mt < 2; mt++)
#pragma unroll
                    for (int nt = 0; nt < 4; nt++)
                        mma16816(c[mt][nt][0], c[mt][nt][1], c[mt][nt][2], c[mt][nt][3],
                                 af[mt][0], af[mt][1], af[mt][2], af[mt][3],
                                 bfr[nt][0], bfr[nt][1]);
            }
            __syncwarp();
            if (lane == 0) mbar_arrive(mbar_base + s * 16 + 8);  // empty[s]
            if (s == STAGES - 1) phase ^= 1;
        }
    }

    __syncthreads();   // producer drained, consumers done; smem reusable

    // ---- stage C to SMEM (consumer warps) ----
    float* epi = (float*)smem;   // [128][EPI_PITCH]
    if (wid < 8) {
        const int wm = wid & 3;
        const int wn = wid >> 2;
#pragma unroll
        for (int mt = 0; mt < 2; mt++) {
#pragma unroll
            for (int nt = 0; nt < 4; nt++) {
                int r0 = wm * 32 + mt * 16 + (lane >> 2);
                int cc = wn * 32 + nt * 8 + (lane & 3) * 2;
                epi[r0 * EPI_PITCH + cc]           = c[mt][nt][0];
                epi[r0 * EPI_PITCH + cc + 1]       = c[mt][nt][1];
                epi[(r0 + 8) * EPI_PITCH + cc]     = c[mt][nt][2];
                epi[(r0 + 8) * EPI_PITCH + cc + 1] = c[mt][nt][3];
            }
        }
    }
    __syncthreads();

    // ---- coalesced gather + mul + add + tanh ----
    if (tid < 256) {
        const int col   = tid & 63;
        const int group = tid >> 6;   // 0..3 -> rows group*32 .. +31
        const float* resid = s_f32 + (size_t)rowBase * NH + colBase;
#pragma unroll 4
        for (int r = 0; r < 32; r++) {
            int row = group * 32 + r;
            int m = rowBase + row;
            int tok = token[m] & (NV - 1);
            float gate = ih_l[(size_t)tok * NH + colBase + col];
            float acc = epi[row * EPI_PITCH + col];
            float v = fast_tanh(resid[(size_t)row * NH + col] + acc * gate);
            out_f32[(size_t)m * NH + colBase + col] = v;
            out_bf[(size_t)m * NH + colBase + col] = __float2bfloat16(v);
        }
    }
}

// ---------------- pre-pass kernels ----------------
__global__ void conv_f32_bf16(const float* __restrict__ s, __nv_bfloat16* __restrict__ o) {
    size_t i = ((size_t)blockIdx.x * blockDim.x + threadIdx.x) * 4;
    float4 v = *reinterpret_cast<const float4*>(s + i);
    __nv_bfloat162* p = reinterpret_cast<__nv_bfloat162*>(o + i);
    p[0] = __floats2bfloat162_rn(v.x, v.y);
    p[1] = __floats2bfloat162_rn(v.z, v.w);
}

// ---------------- launch ----------------
extern "C" void kernel_launch(void* const* d_in, const int* in_sizes, int n_in,
                              void* d_out, int out_size)
{
    const float* state = nullptr;
    const int*   token = nullptr;
    const float* ih    = nullptr;
    const float* hh    = nullptr;
    for (int i = 0; i < n_in; i++) {
        long long sz = in_sizes[i];
        if (sz == (long long)NB * NH)           state = (const float*)d_in[i];
        else if (sz == (long long)NB)           token = (const int*)d_in[i];
        else if (sz == (long long)NL * NV * NH) ih    = (const float*)d_in[i];
        else if (sz == (long long)NL * NH * NH) hh    = (const float*)d_in[i];
    }
    float* out = (float*)d_out;

    float* sf32[2]; __nv_bfloat16* sbf[2]; __nv_bfloat16* hh_bf;
    cudaGetSymbolAddress((void**)&sf32[0], g_sf32);
    sf32[1] = sf32[0] + NB * NH;
    cudaGetSymbolAddress((void**)&sbf[0], g_sbf);
    sbf[1] = sbf[0] + NB * NH;
    cudaGetSymbolAddress((void**)&hh_bf, g_hh_bf);

    cudaFuncSetAttribute(rnn_layer_tc, cudaFuncAttributeMaxDynamicSharedMemorySize, SMEM_TOTAL);

    // pre-pass: state -> bf16 ; hh -> bf16 (layout unchanged, [l][k][n])
    conv_f32_bf16<<<NB * NH / 4 / 256, 256>>>(state, sbf[0]);
    conv_f32_bf16<<<(int)((size_t)NL * NH * NH / 4 / 256), 256>>>(hh, hh_bf);

    dim3 grid(NH / BN, NB / BM);  // (32, 8) = 256 CTAs, 2 per SM
    const float* src_f32 = state;
    for (int l = 0; l < NL; l++) {
        const __nv_bfloat16* a_bf = sbf[l & 1];
        __nv_bfloat16* next_bf = sbf[(l + 1) & 1];
        float* dst_f32 = (l == NL - 1) ? out : sf32[(l + 1) & 1];

        rnn_layer_tc<<<grid, 288, SMEM_TOTAL>>>(
            a_bf, src_f32,
            hh_bf + (size_t)l * NH * NH,
            ih + (size_t)l * NV * NH,
            token, dst_f32, next_bf);

        src_f32 = dst_f32;
    }
}

// round 17
// speedup vs baseline: 1.3286x; 1.3286x over previous
#include <cuda_runtime.h>
#include <cuda_bf16.h>
#include <cstdint>
#include <math.h>

#define NB 1024
#define NH 2048
#define NV 8192
#define NL 8

// ---------------- device scratch (no allocs allowed) ----------------
__device__ float g_sf32[2][NB * NH];                    // fp32 state ping-pong
__device__ __nv_bfloat16 g_sbf[2][NB * NH];             // bf16 state ping-pong
__device__ __nv_bfloat16 g_hh_bf[(size_t)NL * NH * NH]; // hh as bf16, [l][k][n]

// ---------------- PTX helpers (base ISA only; compiles at compute_103) ------
__device__ __forceinline__ uint32_t smem_u32(const void* p) {
    uint32_t a;
    asm("{ .reg .u64 t; cvta.to.shared.u64 t, %1; cvt.u32.u64 %0, t; }" : "=r"(a) : "l"(p));
    return a;
}
__device__ __forceinline__ void cp16(uint32_t saddr, const void* gaddr) {
    asm volatile("cp.async.cg.shared.global [%0], [%1], 16;" :: "r"(saddr), "l"(gaddr) : "memory");
}
__device__ __forceinline__ void cp_commit() {
    asm volatile("cp.async.commit_group;" ::: "memory");
}
__device__ __forceinline__ void mbar_init(uint32_t mbar, uint32_t cnt) {
    asm volatile("mbarrier.init.shared.b64 [%0], %1;" :: "r"(mbar), "r"(cnt) : "memory");
}
__device__ __forceinline__ void mbar_arrive(uint32_t mbar) {
    asm volatile("mbarrier.arrive.shared.b64 _, [%0];" :: "r"(mbar) : "memory");
}
__device__ __forceinline__ void mbar_wait(uint32_t mbar, uint32_t parity) {
    uint32_t done;
    asm volatile("{ .reg .pred p; mbarrier.try_wait.parity.shared.b64 p, [%1], %2; selp.b32 %0,1,0,p; }"
                 : "=r"(done) : "r"(mbar), "r"(parity) : "memory");
    while (!done) {
        asm volatile("{ .reg .pred p; mbarrier.try_wait.parity.shared.b64 p, [%1], %2; selp.b32 %0,1,0,p; }"
                     : "=r"(done) : "r"(mbar), "r"(parity) : "memory");
    }
}
__device__ __forceinline__ void ldsm_x4(uint32_t& d0, uint32_t& d1, uint32_t& d2, uint32_t& d3,
                                        uint32_t addr) {
    asm volatile("ldmatrix.sync.aligned.m8n8.x4.shared.b16 {%0,%1,%2,%3}, [%4];"
                 : "=r"(d0), "=r"(d1), "=r"(d2), "=r"(d3) : "r"(addr));
}
__device__ __forceinline__ void ldsm_x4_t(uint32_t& d0, uint32_t& d1, uint32_t& d2, uint32_t& d3,
                                          uint32_t addr) {
    asm volatile("ldmatrix.sync.aligned.m8n8.x4.trans.shared.b16 {%0,%1,%2,%3}, [%4];"
                 : "=r"(d0), "=r"(d1), "=r"(d2), "=r"(d3) : "r"(addr));
}
__device__ __forceinline__ void mma16816(float& c0, float& c1, float& c2, float& c3,
                                         uint32_t a0, uint32_t a1, uint32_t a2, uint32_t a3,
                                         uint32_t b0, uint32_t b1) {
    asm volatile(
        "mma.sync.aligned.m16n8k16.row.col.f32.bf16.bf16.f32 "
        "{%0,%1,%2,%3}, {%4,%5,%6,%7}, {%8,%9}, {%0,%1,%2,%3};"
        : "+f"(c0), "+f"(c1), "+f"(c2), "+f"(c3)
        : "r"(a0), "r"(a1), "r"(a2), "r"(a3), "r"(b0), "r"(b1));
}
// accurate fast tanh: (e^{2x}-1)/(e^{2x}+1); err ~1e-6; proven identical rel_err
__device__ __forceinline__ float fast_tanh(float x) {
    float xc = fminf(fmaxf(x, -8.0f), 8.0f);
    float e = __expf(2.0f * xc);
    return __fdividef(e - 1.0f, e + 1.0f);
}

// ---------------- tiling (round-7 exact) ----------------
constexpr int BM = 128, BN = 64, BK = 64;
constexpr int NCH = NH / BK;        // 32 K-chunks
constexpr int STAGES = 4;
constexpr int PA_B = 144;           // A smem row pitch (64 bf16 + 8 pad)
constexpr int PB_B = 144;           // B smem row pitch
constexpr int A_BYTES = BM * PA_B;  // 18432
constexpr int B_BYTES = BK * PB_B;  // 9216
constexpr int BUF = A_BYTES + B_BYTES;       // 27648
constexpr int MBAR_OFF = STAGES * BUF;       // 110592
constexpr int SMEM_TOTAL = MBAR_OFF + STAGES * 16;  // 110656
constexpr int EPI_PITCH = 68;                // fp32 elems (epi reuses stage mem)

__global__ __launch_bounds__(288, 2)
void rnn_layer_tc(const __nv_bfloat16* __restrict__ s_bf,
                  const float* __restrict__ s_f32,
                  const __nv_bfloat16* __restrict__ hh_l,  // [NH(k)][NH(n)] bf16
                  const float* __restrict__ ih_l,          // [NV][NH] fp32
                  const int* __restrict__ token,
                  float* __restrict__ out_f32,
                  __nv_bfloat16* __restrict__ out_bf)
{
    extern __shared__ __align__(128) char smem[];
    const uint32_t smem_base = smem_u32(smem);
    const uint32_t mbar_base = smem_base + MBAR_OFF;
    const int tid  = threadIdx.x;
    const int lane = tid & 31;
    const int wid  = tid >> 5;       // 0..7 consumers, 8 producer

    const int colBase = blockIdx.x * BN;
    const int rowBase = blockIdx.y * BM;

    const __nv_bfloat16* a_base = s_bf + (size_t)rowBase * NH;
    const __nv_bfloat16* b_base = hh_l + colBase;

    if (tid == 0) {
#pragma unroll
        for (int s = 0; s < STAGES; s++) {
            mbar_init(mbar_base + s * 16, 32);      // full[s]: producer threads
            mbar_init(mbar_base + s * 16 + 8, 8);   // empty[s]: consumer warps
        }
    }
    __syncthreads();

    float c[2][4][4];
#pragma unroll
    for (int i = 0; i < 2; i++)
#pragma unroll
        for (int j = 0; j < 4; j++)
#pragma unroll
            for (int k = 0; k < 4; k++) c[i][j][k] = 0.0f;

    if (wid == 8) {
        // ================= producer warp =================
        int phase = 1;   // fresh-barrier wait on parity 1 passes immediately
        for (int ch = 0; ch < NCH; ch++) {
            const int s = ch & (STAGES - 1);
            mbar_wait(mbar_base + s * 16 + 8, phase);   // empty[s]
            const uint32_t sa = smem_base + s * BUF;
            const uint32_t sb = sa + A_BYTES;
            const int kt = ch * BK;
#pragma unroll
            for (int i = 0; i < 32; i++) {   // A: 1024 x 16B
                int idx = i * 32 + lane;
                int r = idx >> 3, cc = idx & 7;
                cp16(sa + r * PA_B + cc * 16, a_base + (size_t)r * NH + kt + cc * 8);
            }
#pragma unroll
            for (int i = 0; i < 16; i++) {   // B: 512 x 16B
                int idx = i * 32 + lane;
                int r = idx >> 3, cc = idx & 7;
                cp16(sb + r * PB_B + cc * 16, b_base + (size_t)(kt + r) * NH + cc * 8);
            }
            cp_commit();
            if (ch >= 2) {
                asm volatile("cp.async.wait_group 2;" ::: "memory");
                mbar_arrive(mbar_base + ((ch - 2) & (STAGES - 1)) * 16);  // full
            }
            if (s == STAGES - 1) phase ^= 1;
        }
        asm volatile("cp.async.wait_group 1;" ::: "memory");
        mbar_arrive(mbar_base + ((NCH - 2) & (STAGES - 1)) * 16);
        asm volatile("cp.async.wait_group 0;" ::: "memory");
        mbar_arrive(mbar_base + ((NCH - 1) & (STAGES - 1)) * 16);
    } else {
        // ================= consumer warps (warp tile 32x32) =================
        const int wm = wid & 3;    // 0..3 (M, 32 rows)
        const int wn = wid >> 2;   // 0..1 (N, 32 cols)
        const int lrow = lane & 15;
        const int lseg = (lane >> 4) * 8;
        int phase = 0;
        for (int ch = 0; ch < NCH; ch++) {
            const int s = ch & (STAGES - 1);
            mbar_wait(mbar_base + s * 16, phase);       // full[s]
            const uint32_t sa = smem_base + s * BUF;
            const uint32_t sb = sa + A_BYTES;
#pragma unroll
            for (int ks = 0; ks < 4; ks++) {
                uint32_t af[2][4], bfr[4][2];
#pragma unroll
                for (int mt = 0; mt < 2; mt++) {
                    uint32_t addr = sa + (wm * 32 + mt * 16 + lrow) * PA_B
                                       + (ks * 16 + lseg) * 2;
                    ldsm_x4(af[mt][0], af[mt][1], af[mt][2], af[mt][3], addr);
                }
#pragma unroll
                for (int np = 0; np < 2; np++) {
                    uint32_t addr = sb + (ks * 16 + lrow) * PB_B
                                       + (wn * 32 + np * 16 + lseg) * 2;
                    uint32_t r0, r1, r2, r3;
                    ldsm_x4_t(r0, r1, r2, r3, addr);
                    bfr[np * 2 + 0][0] = r0; bfr[np * 2 + 0][1] = r1;
                    bfr[np * 2 + 1][0] = r2; bfr[np * 2 + 1][1] = r3;
                }
#pragma unroll
                for (int mt = 0; mt < 2; mt++)
#pragma unroll
                    for (int nt = 0; nt < 4; nt++)
                        mma16816(c[mt][nt][0], c[mt][nt][1], c[mt][nt][2], c[mt][nt][3],
                                 af[mt][0], af[mt][1], af[mt][2], af[mt][3],
                                 bfr[nt][0], bfr[nt][1]);
            }
            __syncwarp();
            if (lane == 0) mbar_arrive(mbar_base + s * 16 + 8);  // empty[s]
            if (s == STAGES - 1) phase ^= 1;
        }
    }

    __syncthreads();   // producer drained, consumers done; smem reusable

    // ---- stage C to SMEM (consumer warps) ----
    float* epi = (float*)smem;   // [128][EPI_PITCH]
    if (wid < 8) {
        const int wm = wid & 3;
        const int wn = wid >> 2;
#pragma unroll
        for (int mt = 0; mt < 2; mt++) {
#pragma unroll
            for (int nt = 0; nt < 4; nt++) {
                int r0 = wm * 32 + mt * 16 + (lane >> 2);
                int cc = wn * 32 + nt * 8 + (lane & 3) * 2;
                epi[r0 * EPI_PITCH + cc]           = c[mt][nt][0];
                epi[r0 * EPI_PITCH + cc + 1]       = c[mt][nt][1];
                epi[(r0 + 8) * EPI_PITCH + cc]     = c[mt][nt][2];
                epi[(r0 + 8) * EPI_PITCH + cc + 1] = c[mt][nt][3];
            }
        }
    }
    __syncthreads();

    // ---- vectorized (float2) gather + mul + add + tanh ----
    if (tid < 256) {
        const int col2  = tid & 31;    // 32 float2 cover 64 cols
        const int group = tid >> 5;    // 0..7 -> rows group*16 .. +15
        const float* resid = s_f32 + (size_t)rowBase * NH + colBase;
#pragma unroll 4
        for (int r = 0; r < 16; r++) {
            int row = group * 16 + r;
            int m = rowBase + row;
            int tok = token[m] & (NV - 1);
            float2 gate = *reinterpret_cast<const float2*>(
                &ih_l[(size_t)tok * NH + colBase + col2 * 2]);
            float2 rs = *reinterpret_cast<const float2*>(
                &resid[(size_t)row * NH + col2 * 2]);
            float2 ac = *reinterpret_cast<const float2*>(
                &epi[row * EPI_PITCH + col2 * 2]);
            float v0 = fast_tanh(rs.x + ac.x * gate.x);
            float v1 = fast_tanh(rs.y + ac.y * gate.y);
            *reinterpret_cast<float2*>(
                &out_f32[(size_t)m * NH + colBase + col2 * 2]) = make_float2(v0, v1);
            *reinterpret_cast<__nv_bfloat162*>(
                &out_bf[(size_t)m * NH + colBase + col2 * 2]) =
                __floats2bfloat162_rn(v0, v1);
        }
    }
}

// ---------------- pre-pass: f32 -> bf16, 8 elems/thread ----------------
__global__ void conv_f32_bf16(const float* __restrict__ s, __nv_bfloat16* __restrict__ o) {
    size_t i = ((size_t)blockIdx.x * blockDim.x + threadIdx.x) * 8;
    float4 v0 = *reinterpret_cast<const float4*>(s + i);
    float4 v1 = *reinterpret_cast<const float4*>(s + i + 4);
    uint4 out;
    __nv_bfloat162 b0 = __floats2bfloat162_rn(v0.x, v0.y);
    __nv_bfloat162 b1 = __floats2bfloat162_rn(v0.z, v0.w);
    __nv_bfloat162 b2 = __floats2bfloat162_rn(v1.x, v1.y);
    __nv_bfloat162 b3 = __floats2bfloat162_rn(v1.z, v1.w);
    out.x = *reinterpret_cast<uint32_t*>(&b0);
    out.y = *reinterpret_cast<uint32_t*>(&b1);
    out.z = *reinterpret_cast<uint32_t*>(&b2);
    out.w = *reinterpret_cast<uint32_t*>(&b3);
    *reinterpret_cast<uint4*>(o + i) = out;
}

// ---------------- launch ----------------
extern "C" void kernel_launch(void* const* d_in, const int* in_sizes, int n_in,
                              void* d_out, int out_size)
{
    const float* state = nullptr;
    const int*   token = nullptr;
    const float* ih    = nullptr;
    const float* hh    = nullptr;
    for (int i = 0; i < n_in; i++) {
        long long sz = in_sizes[i];
        if (sz == (long long)NB * NH)           state = (const float*)d_in[i];
        else if (sz == (long long)NB)           token = (const int*)d_in[i];
        else if (sz == (long long)NL * NV * NH) ih    = (const float*)d_in[i];
        else if (sz == (long long)NL * NH * NH) hh    = (const float*)d_in[i];
    }
    float* out = (float*)d_out;

    float* sf32[2]; __nv_bfloat16* sbf[2]; __nv_bfloat16* hh_bf;
    cudaGetSymbolAddress((void**)&sf32[0], g_sf32);
    sf32[1] = sf32[0] + NB * NH;
    cudaGetSymbolAddress((void**)&sbf[0], g_sbf);
    sbf[1] = sbf[0] + NB * NH;
    cudaGetSymbolAddress((void**)&hh_bf, g_hh_bf);

    cudaFuncSetAttribute(rnn_layer_tc, cudaFuncAttributeMaxDynamicSharedMemorySize, SMEM_TOTAL);

    // pre-pass: state -> bf16 ; hh -> bf16 (layout unchanged, [l][k][n])
    conv_f32_bf16<<<NB * NH / 8 / 256, 256>>>(state, sbf[0]);
    conv_f32_bf16<<<(int)((size_t)NL * NH * NH / 8 / 256), 256>>>(hh, hh_bf);

    dim3 grid(NH / BN, NB / BM);  // (32, 8) = 256 CTAs, 2 per SM
    const float* src_f32 = state;
    for (int l = 0; l < NL; l++) {
        const __nv_bfloat16* a_bf = sbf[l & 1];
        __nv_bfloat16* next_bf = sbf[(l + 1) & 1];
        float* dst_f32 = (l == NL - 1) ? out : sf32[(l + 1) & 1];

        rnn_layer_tc<<<grid, 288, SMEM_TOTAL>>>(
            a_bf, src_f32,
            hh_bf + (size_t)l * NH * NH,
            ih + (size_t)l * NV * NH,
            token, dst_f32, next_bf);

        src_f32 = dst_f32;
    }
}